// round 8
// baseline (speedup 1.0000x reference)
#include <cuda_runtime.h>
#include <math_constants.h>

#define BATCH 256
#define SEGMAX 8200   // level-2 parents ~2750 (+1 sentinel); headroom
#define RROWS 4       // batch rows per warp in level-2 kernel (32-reg sweet spot)
#define SMEMN 2048    // smem staging capacity for level-1 results

// Per-level segment tables: g_seg[lvl][i] = ABSOLUTE node index of first child
// of parent slot i; g_seg[lvl][P] = end. g_pbase[lvl] = first parent node index.
// g_cend[lvl] = absolute end of the child region for that level.
__device__ int g_seg[3][SEGMAX];
__device__ int g_pbase[3];
__device__ int g_cend[3];

// Merged prep: blockIdx.y = level. Decode flat_idx (i*M+j) into absolute
// contiguous per-parent child ranges.
__global__ void prep_all_kernel(
    const int* __restrict__ f0, const int* __restrict__ M0,
    const int* __restrict__ c0, const int* __restrict__ p0, int N0, int P0,
    const int* __restrict__ f1, const int* __restrict__ M1,
    const int* __restrict__ c1, const int* __restrict__ p1, int N1, int P1,
    const int* __restrict__ f2, const int* __restrict__ M2,
    const int* __restrict__ c2, const int* __restrict__ p2, int N2, int P2) {
    int lvl = blockIdx.y;
    const int* f; const int* Mp; const int* c; const int* p; int N, P;
    if (lvl == 0) { f = f0; Mp = M0; c = c0; p = p0; N = N0; P = P0; }
    else if (lvl == 1) { f = f1; Mp = M1; c = c1; p = p1; N = N1; P = P1; }
    else { f = f2; Mp = M2; c = c2; p = p2; N = N2; P = P2; }

    int k = blockIdx.x * blockDim.x + threadIdx.x;
    int M = Mp[0];
    int* seg = g_seg[lvl];
    if (k < N) {
        int i = f[k] / M;
        if (k == 0 || (f[k - 1] / M) != i) seg[i] = c[0] + k;
    }
    if (k == 0) {
        seg[P] = c[0] + N;
        g_pbase[lvl] = p[0];
        g_cend[lvl] = c[0] + N;
    }
}

// Level-2 (deepest): one warp handles RROWS=4 batch rows of one parent segment.
// Fast path: UNPREDICATED loads/stores of the full 64-slot window starting at
// cbase. Slots beyond the segment end hold neighboring leaves; storing them
// writes the same copied value the owner warp writes (benign, deterministic).
// Values are masked to -inf only for the exp accumulation. The window is valid
// whenever cbase+64 <= leafEnd (all but the last segment or two).
__global__ void __launch_bounds__(256)
level2_kernel(const float* __restrict__ in, float* __restrict__ out,
              int P, int num_nodes) {
    int i = blockIdx.x * (blockDim.x >> 5) + (threadIdx.x >> 5);
    if (i >= P) return;
    int lane = threadIdx.x & 31;

    const int* seg = g_seg[2];
    int cbase = seg[i];
    int n = seg[i + 1] - cbase;
    int pnode = g_pbase[2] + i;
    int leafEnd = g_cend[2];

    size_t rowoff = (size_t)(blockIdx.y * RROWS) * num_nodes;
    const float* srcBase = in + rowoff;
    float*       dstBase = out + rowoff;

    const float NEG_INF = -CUDART_INF_F;
    float acc[RROWS];

    if (n <= 64 && cbase + 64 <= leafEnd) {
        // Fast path: no load/store predication at all.
        float v[RROWS][2];
#pragma unroll
        for (int r = 0; r < RROWS; r++) {
            const float* src = srcBase + (size_t)r * num_nodes + cbase;
            v[r][0] = src[lane];
            v[r][1] = src[lane + 32];
        }
#pragma unroll
        for (int r = 0; r < RROWS; r++) {
            float* dst = dstBase + (size_t)r * num_nodes + cbase;
            dst[lane]      = v[r][0];
            dst[lane + 32] = v[r][1];
        }
        bool m0 = lane < n;          // row-invariant masks
        bool m1 = lane + 32 < n;
#pragma unroll
        for (int r = 0; r < RROWS; r++) {
            float x0 = m0 ? v[r][0] : NEG_INF;   // __expf(-inf)=0
            float x1 = m1 ? v[r][1] : NEG_INF;
            acc[r] = __expf(x0) + __expf(x1);
        }
    } else if (n <= 64) {
        // Predicated path (last segment(s) near the leaf-region end).
        float v[RROWS][2];
#pragma unroll
        for (int r = 0; r < RROWS; r++) {
            const float* src = srcBase + (size_t)r * num_nodes;
            v[r][0] = (lane < n)      ? src[cbase + lane]      : NEG_INF;
            v[r][1] = (lane + 32 < n) ? src[cbase + lane + 32] : NEG_INF;
        }
#pragma unroll
        for (int r = 0; r < RROWS; r++) {
            float* dst = dstBase + (size_t)r * num_nodes;
            if (lane < n)      dst[cbase + lane]      = v[r][0];
            if (lane + 32 < n) dst[cbase + lane + 32] = v[r][1];
        }
#pragma unroll
        for (int r = 0; r < RROWS; r++)
            acc[r] = __expf(v[r][0]) + __expf(v[r][1]);
    } else {
        // Generic fallback (not expected for this tree shape).
#pragma unroll
        for (int r = 0; r < RROWS; r++) acc[r] = 0.0f;
        for (int k = lane; k < n; k += 32) {
#pragma unroll
            for (int r = 0; r < RROWS; r++) {
                float x = srcBase[(size_t)r * num_nodes + cbase + k];
                dstBase[(size_t)r * num_nodes + cbase + k] = x;
                acc[r] += __expf(x);
            }
        }
    }

    // Grouped reduction: butterfly {16,8} on all 4 accs -> each acc[r] holds
    // the sum over lanes congruent mod 8; 8-lane group g=lane>>3 takes acc[g];
    // butterfly {4,2,1} finishes within the group.
#pragma unroll
    for (int r = 0; r < RROWS; r++) {
        acc[r] += __shfl_xor_sync(0xffffffffu, acc[r], 16);
        acc[r] += __shfl_xor_sync(0xffffffffu, acc[r], 8);
    }
    int g = lane >> 3;
    float w = acc[0];
    w = (g == 1) ? acc[1] : w;
    w = (g == 2) ? acc[2] : w;
    w = (g == 3) ? acc[3] : w;
    w += __shfl_xor_sync(0xffffffffu, w, 4);
    w += __shfl_xor_sync(0xffffffffu, w, 2);
    w += __shfl_xor_sync(0xffffffffu, w, 1);

    if ((lane & 7) == 0) {
        float lse = __logf(w);
        const float* rowIn  = srcBase + (size_t)g * num_nodes;
        float*       rowOut = dstBase + (size_t)g * num_nodes;
        rowOut[pnode] = fmaxf(rowIn[pnode], lse);
    }
}

// Fused levels 1 and 0: one block (4 warps) per batch row.
// Phase A: warps sweep the P1 level-1 segments (children are level-2 nodes in
// out, L2-hot), write parent updates, stage updated values in smem.
// Phase B: warp 0 computes the root LSE over the level-1 parents.
__global__ void level01_kernel(const float* __restrict__ in, float* __restrict__ out,
                               int P1, int num_nodes) {
    __shared__ float l1[SMEMN];
    int b = blockIdx.x;
    int wid = threadIdx.x >> 5;
    int lane = threadIdx.x & 31;
    int nwarps = blockDim.x >> 5;

    const float* rowIn  = in  + (size_t)b * num_nodes;
    float*       rowOut = out + (size_t)b * num_nodes;

    const int* seg1 = g_seg[1];
    int p1base = g_pbase[1];
    const float NEG_INF = -CUDART_INF_F;

    for (int i = wid; i < P1; i += nwarps) {
        int cbase = seg1[i];
        int n = seg1[i + 1] - cbase;
        float acc = 0.0f;
        if (n <= 64) {
#pragma unroll
            for (int t = 0; t < 2; t++) {
                int k = lane + t * 32;
                float x = (k < n) ? rowOut[cbase + k] : NEG_INF;
                acc += __expf(x);
            }
        } else {
            for (int k = lane; k < n; k += 32) acc += __expf(rowOut[cbase + k]);
        }
#pragma unroll
        for (int o = 16; o; o >>= 1) acc += __shfl_xor_sync(0xffffffffu, acc, o);
        if (lane == 0) {
            int pnode = p1base + i;
            float val = fmaxf(rowIn[pnode], __logf(acc));
            rowOut[pnode] = val;
            if (i < SMEMN) l1[i] = val;
        }
    }
    __syncthreads();

    if (wid == 0) {
        const int* seg0 = g_seg[0];
        int cbase = seg0[0];
        int n = seg0[1] - cbase;         // = P1 (root children are level-1 nodes)
        bool use_smem = (n == P1) && (P1 <= SMEMN);
        float acc = 0.0f;
        if (n <= 128) {
#pragma unroll
            for (int t = 0; t < 4; t++) {
                int k = lane + t * 32;
                float x;
                if (k < n) x = use_smem ? l1[k] : rowOut[cbase + k];
                else       x = NEG_INF;
                acc += __expf(x);
            }
        } else {
            for (int k = lane; k < n; k += 32)
                acc += __expf(use_smem ? l1[k] : rowOut[cbase + k]);
        }
#pragma unroll
        for (int o = 16; o; o >>= 1) acc += __shfl_xor_sync(0xffffffffu, acc, o);
        if (lane == 0) {
            int pnode = g_pbase[0];
            rowOut[pnode] = fmaxf(rowIn[pnode], __logf(acc));
        }
    }
}

extern "C" void kernel_launch(void* const* d_in, const int* in_sizes, int n_in,
                              void* d_out, int out_size) {
    // metadata order: scores, p0,f0,c0,P0,M0, p1,f1,c1,P1,M1, p2,f2,c2,P2,M2
    const float* scores = (const float*)d_in[0];
    const int* p0 = (const int*)d_in[1];
    const int* f0 = (const int*)d_in[2];
    const int* c0 = (const int*)d_in[3];
    const int* M0 = (const int*)d_in[5];
    const int* p1 = (const int*)d_in[6];
    const int* f1 = (const int*)d_in[7];
    const int* c1 = (const int*)d_in[8];
    const int* M1 = (const int*)d_in[10];
    const int* p2 = (const int*)d_in[11];
    const int* f2 = (const int*)d_in[12];
    const int* c2 = (const int*)d_in[13];
    const int* M2 = (const int*)d_in[15];

    int P0 = in_sizes[1],  N0 = in_sizes[2];
    int P1 = in_sizes[6],  N1 = in_sizes[7];
    int P2 = in_sizes[11], N2 = in_sizes[12];
    int num_nodes = in_sizes[0] / BATCH;
    float* out = (float*)d_out;

    // One merged prep launch covering all three levels.
    int maxN = N0 > N1 ? N0 : N1; if (N2 > maxN) maxN = N2;
    dim3 pgrid((maxN + 255) / 256, 3);
    prep_all_kernel<<<pgrid, 256>>>(f0, M0, c0, p0, N0, P0,
                                    f1, M1, c1, p1, N1, P1,
                                    f2, M2, c2, p2, N2, P2);

    // Level 2: dominant kernel (fused copy + LSE), 4 rows per warp.
    {
        const int WPB = 8;
        dim3 grid((P2 + WPB - 1) / WPB, BATCH / RROWS);
        level2_kernel<<<grid, WPB * 32>>>(scores, out, P2, num_nodes);
    }
    // Levels 1 + 0 fused: one block per batch row.
    level01_kernel<<<BATCH, 128>>>(scores, out, P1, num_nodes);
}

// round 9
// speedup vs baseline: 1.1206x; 1.1206x over previous
#include <cuda_runtime.h>
#include <math_constants.h>

#define BATCH 256
#define SEGMAX 8200   // level-2 parents ~2750 (+1 sentinel); headroom
#define RROWS 4       // batch rows per warp (32-reg sweet spot)

// Per-level segment tables: g_seg[lvl][i] = ABSOLUTE node index of first child
// of parent slot i; g_seg[lvl][P] = end. g_pbase[lvl] = first parent node index.
// g_cend[lvl] = absolute end of the child region for that level.
__device__ int g_seg[3][SEGMAX];
__device__ int g_pbase[3];
__device__ int g_cend[3];

// Merged prep: blockIdx.y = level. Decode flat_idx (i*M+j) into absolute
// contiguous per-parent child ranges.
__global__ void prep_all_kernel(
    const int* __restrict__ f0, const int* __restrict__ M0,
    const int* __restrict__ c0, const int* __restrict__ p0, int N0, int P0,
    const int* __restrict__ f1, const int* __restrict__ M1,
    const int* __restrict__ c1, const int* __restrict__ p1, int N1, int P1,
    const int* __restrict__ f2, const int* __restrict__ M2,
    const int* __restrict__ c2, const int* __restrict__ p2, int N2, int P2) {
    int lvl = blockIdx.y;
    const int* f; const int* Mp; const int* c; const int* p; int N, P;
    if (lvl == 0) { f = f0; Mp = M0; c = c0; p = p0; N = N0; P = P0; }
    else if (lvl == 1) { f = f1; Mp = M1; c = c1; p = p1; N = N1; P = P1; }
    else { f = f2; Mp = M2; c = c2; p = p2; N = N2; P = P2; }

    int k = blockIdx.x * blockDim.x + threadIdx.x;
    int M = Mp[0];
    int* seg = g_seg[lvl];
    if (k < N) {
        int i = f[k] / M;
        if (k == 0 || (f[k - 1] / M) != i) seg[i] = c[0] + k;
    }
    if (k == 0) {
        seg[P] = c[0] + N;
        g_pbase[lvl] = p[0];
        g_cend[lvl] = c[0] + N;
    }
}

// Shared epilogue: grouped reduction over 4 row-accumulators + 4 parallel
// parent updates. acc[r] = partial sums across lanes.
__device__ __forceinline__ void reduce_and_update(
    float acc[RROWS], int lane, int pnode,
    const float* srcBase, float* dstBase, int num_nodes) {
#pragma unroll
    for (int r = 0; r < RROWS; r++) {
        acc[r] += __shfl_xor_sync(0xffffffffu, acc[r], 16);
        acc[r] += __shfl_xor_sync(0xffffffffu, acc[r], 8);
    }
    int g = lane >> 3;
    float w = acc[0];
    w = (g == 1) ? acc[1] : w;
    w = (g == 2) ? acc[2] : w;
    w = (g == 3) ? acc[3] : w;
    w += __shfl_xor_sync(0xffffffffu, w, 4);
    w += __shfl_xor_sync(0xffffffffu, w, 2);
    w += __shfl_xor_sync(0xffffffffu, w, 1);

    if ((lane & 7) == 0) {
        float lse = __logf(w);
        const float* rowIn  = srcBase + (size_t)g * num_nodes;
        float*       rowOut = dstBase + (size_t)g * num_nodes;
        rowOut[pnode] = fmaxf(rowIn[pnode], lse);
    }
}

// Level-2 (deepest): one warp handles RROWS=4 batch rows of one parent segment.
// Fast path: UNPREDICATED loads/stores of the full 64-slot window at cbase.
// Out-of-segment slots hold neighboring leaves; storing them writes the same
// copied value the owner warp writes (benign, deterministic). Values masked to
// -inf only for the exp accumulation.
__global__ void __launch_bounds__(256)
level2_kernel(const float* __restrict__ in, float* __restrict__ out,
              int P, int num_nodes) {
    int i = blockIdx.x * (blockDim.x >> 5) + (threadIdx.x >> 5);
    if (i >= P) return;
    int lane = threadIdx.x & 31;

    const int* seg = g_seg[2];
    int cbase = seg[i];
    int n = seg[i + 1] - cbase;
    int pnode = g_pbase[2] + i;
    int leafEnd = g_cend[2];

    size_t rowoff = (size_t)(blockIdx.y * RROWS) * num_nodes;
    const float* srcBase = in + rowoff;
    float*       dstBase = out + rowoff;

    const float NEG_INF = -CUDART_INF_F;
    float acc[RROWS];

    if (n <= 64 && cbase + 64 <= leafEnd) {
        float v[RROWS][2];
#pragma unroll
        for (int r = 0; r < RROWS; r++) {
            const float* src = srcBase + (size_t)r * num_nodes + cbase;
            v[r][0] = src[lane];
            v[r][1] = src[lane + 32];
        }
#pragma unroll
        for (int r = 0; r < RROWS; r++) {
            float* dst = dstBase + (size_t)r * num_nodes + cbase;
            dst[lane]      = v[r][0];
            dst[lane + 32] = v[r][1];
        }
        bool m0 = lane < n;
        bool m1 = lane + 32 < n;
#pragma unroll
        for (int r = 0; r < RROWS; r++) {
            float x0 = m0 ? v[r][0] : NEG_INF;   // __expf(-inf)=0
            float x1 = m1 ? v[r][1] : NEG_INF;
            acc[r] = __expf(x0) + __expf(x1);
        }
    } else if (n <= 64) {
        float v[RROWS][2];
#pragma unroll
        for (int r = 0; r < RROWS; r++) {
            const float* src = srcBase + (size_t)r * num_nodes;
            v[r][0] = (lane < n)      ? src[cbase + lane]      : NEG_INF;
            v[r][1] = (lane + 32 < n) ? src[cbase + lane + 32] : NEG_INF;
        }
#pragma unroll
        for (int r = 0; r < RROWS; r++) {
            float* dst = dstBase + (size_t)r * num_nodes;
            if (lane < n)      dst[cbase + lane]      = v[r][0];
            if (lane + 32 < n) dst[cbase + lane + 32] = v[r][1];
        }
#pragma unroll
        for (int r = 0; r < RROWS; r++)
            acc[r] = __expf(v[r][0]) + __expf(v[r][1]);
    } else {
#pragma unroll
        for (int r = 0; r < RROWS; r++) acc[r] = 0.0f;
        for (int k = lane; k < n; k += 32) {
#pragma unroll
            for (int r = 0; r < RROWS; r++) {
                float x = srcBase[(size_t)r * num_nodes + cbase + k];
                dstBase[(size_t)r * num_nodes + cbase + k] = x;
                acc[r] += __expf(x);
            }
        }
    }

    reduce_and_update(acc, lane, pnode, srcBase, dstBase, num_nodes);
}

// Upper levels (1 and 0): one warp handles RROWS=4 batch rows of one parent
// segment. Children are read from OUT (already updated by the deeper level,
// L2-hot). Parent nodes at this depth are untouched by deeper levels, so
// in[pnode] == out[pnode] and max(in[pnode], lse) is correct. No bulk copy.
// Fast path: unpredicated loads of a SLOTS*32 window (over-read hits valid
// neighboring nodes), masked at the exp step.
template <int SLOTS>
__global__ void levelr_kernel(const float* __restrict__ in, float* __restrict__ out,
                              int P, int num_nodes, int lvl) {
    int i = blockIdx.x * (blockDim.x >> 5) + (threadIdx.x >> 5);
    if (i >= P) return;
    int lane = threadIdx.x & 31;

    const int* seg = g_seg[lvl];
    int cbase = seg[i];
    int n = seg[i + 1] - cbase;
    int pnode = g_pbase[lvl] + i;
    int cend = g_cend[lvl];

    size_t rowoff = (size_t)(blockIdx.y * RROWS) * num_nodes;
    const float* srcBase = in + rowoff;
    float*       dstBase = out + rowoff;

    const float NEG_INF = -CUDART_INF_F;
    float acc[RROWS];

    if (n <= SLOTS * 32 && cbase + SLOTS * 32 <= cend) {
        float v[RROWS][SLOTS];
#pragma unroll
        for (int r = 0; r < RROWS; r++) {
            const float* src = dstBase + (size_t)r * num_nodes + cbase;
#pragma unroll
            for (int t = 0; t < SLOTS; t++) v[r][t] = src[lane + t * 32];
        }
#pragma unroll
        for (int r = 0; r < RROWS; r++) {
            acc[r] = 0.0f;
#pragma unroll
            for (int t = 0; t < SLOTS; t++) {
                float x = (lane + t * 32 < n) ? v[r][t] : NEG_INF;
                acc[r] += __expf(x);
            }
        }
    } else {
#pragma unroll
        for (int r = 0; r < RROWS; r++) acc[r] = 0.0f;
        for (int k = lane; k < n; k += 32) {
#pragma unroll
            for (int r = 0; r < RROWS; r++)
                acc[r] += __expf(dstBase[(size_t)r * num_nodes + cbase + k]);
        }
    }

    reduce_and_update(acc, lane, pnode, srcBase, dstBase, num_nodes);
}

extern "C" void kernel_launch(void* const* d_in, const int* in_sizes, int n_in,
                              void* d_out, int out_size) {
    // metadata order: scores, p0,f0,c0,P0,M0, p1,f1,c1,P1,M1, p2,f2,c2,P2,M2
    const float* scores = (const float*)d_in[0];
    const int* p0 = (const int*)d_in[1];
    const int* f0 = (const int*)d_in[2];
    const int* c0 = (const int*)d_in[3];
    const int* M0 = (const int*)d_in[5];
    const int* p1 = (const int*)d_in[6];
    const int* f1 = (const int*)d_in[7];
    const int* c1 = (const int*)d_in[8];
    const int* M1 = (const int*)d_in[10];
    const int* p2 = (const int*)d_in[11];
    const int* f2 = (const int*)d_in[12];
    const int* c2 = (const int*)d_in[13];
    const int* M2 = (const int*)d_in[15];

    int P0 = in_sizes[1],  N0 = in_sizes[2];
    int P1 = in_sizes[6],  N1 = in_sizes[7];
    int P2 = in_sizes[11], N2 = in_sizes[12];
    int num_nodes = in_sizes[0] / BATCH;
    float* out = (float*)d_out;

    // One merged prep launch covering all three levels.
    int maxN = N0 > N1 ? N0 : N1; if (N2 > maxN) maxN = N2;
    dim3 pgrid((maxN + 255) / 256, 3);
    prep_all_kernel<<<pgrid, 256>>>(f0, M0, c0, p0, N0, P0,
                                    f1, M1, c1, p1, N1, P1,
                                    f2, M2, c2, p2, N2, P2);

    const int WPB = 8;  // warps per block
    // Level 2: dominant kernel (fused leaf copy + LSE), 4 rows per warp.
    {
        dim3 grid((P2 + WPB - 1) / WPB, BATCH / RROWS);
        level2_kernel<<<grid, WPB * 32>>>(scores, out, P2, num_nodes);
    }
    // Level 1: massively parallel (P1 x 64 warps), children L2-hot in out.
    {
        dim3 grid((P1 + WPB - 1) / WPB, BATCH / RROWS);
        levelr_kernel<2><<<grid, WPB * 32>>>(scores, out, P1, num_nodes, 1);
    }
    // Level 0 (root): P0=1 segment, n~100 -> 4 slots; 64 warps total.
    {
        dim3 grid(1, BATCH / RROWS);
        levelr_kernel<4><<<grid, 32>>>(scores, out, P0, num_nodes, 0);
    }
}

// round 10
// speedup vs baseline: 1.3213x; 1.1791x over previous
#include <cuda_runtime.h>
#include <math_constants.h>

#define BATCH 256
#define SEGMAX 8200
#define RROWS 4
#define TPB 256
#define WPB (TPB / 32)
#define RGROUPS (BATCH / RROWS)   // 64

__device__ int g_seg[3][SEGMAX];
__device__ int g_pbase[3];
__device__ int g_cend[3];
__device__ unsigned g_barcnt = 0;
__device__ unsigned g_bargen = 0;

// Sense-reversing grid barrier. ALL threads of ALL (co-resident) blocks must call.
__device__ __forceinline__ void grid_barrier() {
    __threadfence();
    __syncthreads();
    if (threadIdx.x == 0) {
        unsigned gen = atomicAdd(&g_bargen, 0u);
        if (atomicAdd(&g_barcnt, 1u) == (unsigned)gridDim.x - 1u) {
            atomicExch(&g_barcnt, 0u);
            __threadfence();
            atomicAdd(&g_bargen, 1u);   // release
        } else {
            while (atomicAdd(&g_bargen, 0u) == gen) { }   // acquire spin
        }
    }
    __syncthreads();
}

// Grouped reduction over 4 row-accumulators + 4 parallel parent updates.
__device__ __forceinline__ void reduce_and_update(
    float acc[RROWS], int lane, int pnode,
    const float* srcBase, float* dstBase, int num_nodes) {
#pragma unroll
    for (int r = 0; r < RROWS; r++) {
        acc[r] += __shfl_xor_sync(0xffffffffu, acc[r], 16);
        acc[r] += __shfl_xor_sync(0xffffffffu, acc[r], 8);
    }
    int g = lane >> 3;
    float w = acc[0];
    w = (g == 1) ? acc[1] : w;
    w = (g == 2) ? acc[2] : w;
    w = (g == 3) ? acc[3] : w;
    w += __shfl_xor_sync(0xffffffffu, w, 4);
    w += __shfl_xor_sync(0xffffffffu, w, 2);
    w += __shfl_xor_sync(0xffffffffu, w, 1);
    if ((lane & 7) == 0) {
        float lse = __logf(w);
        const float* rowIn  = srcBase + (size_t)g * num_nodes;
        float*       rowOut = dstBase + (size_t)g * num_nodes;
        rowOut[pnode] = fmaxf(rowIn[pnode], lse);
    }
}

// Upper-level segment LSE (children read from out via __ldcg, cross-SM safe).
template <int SLOTS>
__device__ __forceinline__ void upper_seg(
    const float* __restrict__ in, float* __restrict__ out,
    int lvl, int i, int rg, int lane, int num_nodes) {
    const int* seg = g_seg[lvl];
    int cbase = seg[i];
    int n = seg[i + 1] - cbase;
    int pnode = g_pbase[lvl] + i;
    int cend = g_cend[lvl];

    size_t rowoff = (size_t)(rg * RROWS) * num_nodes;
    const float* srcBase = in + rowoff;
    float*       dstBase = out + rowoff;
    const float NEG_INF = -CUDART_INF_F;
    float acc[RROWS];

    if (n <= SLOTS * 32 && cbase + SLOTS * 32 <= cend) {
        float v[RROWS][SLOTS];
#pragma unroll
        for (int r = 0; r < RROWS; r++) {
            const float* src = dstBase + (size_t)r * num_nodes + cbase;
#pragma unroll
            for (int t = 0; t < SLOTS; t++) v[r][t] = __ldcg(src + lane + t * 32);
        }
#pragma unroll
        for (int r = 0; r < RROWS; r++) {
            acc[r] = 0.0f;
#pragma unroll
            for (int t = 0; t < SLOTS; t++) {
                float x = (lane + t * 32 < n) ? v[r][t] : NEG_INF;
                acc[r] += __expf(x);
            }
        }
    } else {
#pragma unroll
        for (int r = 0; r < RROWS; r++) acc[r] = 0.0f;
        for (int k = lane; k < n; k += 32)
#pragma unroll
            for (int r = 0; r < RROWS; r++)
                acc[r] += __expf(__ldcg(dstBase + (size_t)r * num_nodes + cbase + k));
    }
    reduce_and_update(acc, lane, pnode, srcBase, dstBase, num_nodes);
}

__global__ void __launch_bounds__(TPB)
fused_kernel(const float* __restrict__ in, float* __restrict__ out,
             const int* __restrict__ f0, const int* __restrict__ M0,
             const int* __restrict__ c0, const int* __restrict__ p0, int N0, int P0,
             const int* __restrict__ f1, const int* __restrict__ M1,
             const int* __restrict__ c1, const int* __restrict__ p1, int N1, int P1,
             const int* __restrict__ f2, const int* __restrict__ M2,
             const int* __restrict__ c2, const int* __restrict__ p2, int N2, int P2,
             int num_nodes) {
    int lane = threadIdx.x & 31;
    int gw = blockIdx.x * WPB + (threadIdx.x >> 5);
    int nw = gridDim.x * WPB;
    int tid = blockIdx.x * TPB + threadIdx.x;
    int nthreads = gridDim.x * TPB;

    // ---- Phase P: segment decode for all three levels ----
    {
        // level 2
        int Mv = M2[0];
        for (int k = tid; k < N2; k += nthreads) {
            int i = f2[k] / Mv;
            if (k == 0 || (f2[k - 1] / Mv) != i) g_seg[2][i] = c2[0] + k;
        }
        // level 1
        Mv = M1[0];
        for (int k = tid; k < N1; k += nthreads) {
            int i = f1[k] / Mv;
            if (k == 0 || (f1[k - 1] / Mv) != i) g_seg[1][i] = c1[0] + k;
        }
        // level 0
        Mv = M0[0];
        for (int k = tid; k < N0; k += nthreads) {
            int i = f0[k] / Mv;
            if (k == 0 || (f0[k - 1] / Mv) != i) g_seg[0][i] = c0[0] + k;
        }
        if (tid == 0) {
            g_seg[2][P2] = c2[0] + N2; g_pbase[2] = p2[0]; g_cend[2] = c2[0] + N2;
            g_seg[1][P1] = c1[0] + N1; g_pbase[1] = p1[0]; g_cend[1] = c1[0] + N1;
            g_seg[0][P0] = c0[0] + N0; g_pbase[0] = p0[0]; g_cend[0] = c0[0] + N0;
        }
    }
    grid_barrier();

    // ---- Phase 2 (leaves): fused copy in->out + LSE into level-2 parents ----
    {
        const int* seg = g_seg[2];
        int pbase = g_pbase[2];
        int leafEnd = g_cend[2];
        const float NEG_INF = -CUDART_INF_F;
        int total = P2 << 6;   // P2 segments x 64 rowgroups
        for (int item = gw; item < total; item += nw) {
            int i = item >> 6;
            int rg = item & 63;
            int cbase = seg[i];
            int n = seg[i + 1] - cbase;
            int pnode = pbase + i;

            size_t rowoff = (size_t)(rg * RROWS) * num_nodes;
            const float* srcBase = in + rowoff;
            float*       dstBase = out + rowoff;
            float acc[RROWS];

            if (n <= 64 && cbase + 64 <= leafEnd) {
                // Unpredicated 64-slot window; out-of-segment stores write the
                // same copied value the owner warp writes (benign).
                float v[RROWS][2];
#pragma unroll
                for (int r = 0; r < RROWS; r++) {
                    const float* src = srcBase + (size_t)r * num_nodes + cbase;
                    v[r][0] = src[lane];
                    v[r][1] = src[lane + 32];
                }
#pragma unroll
                for (int r = 0; r < RROWS; r++) {
                    float* dst = dstBase + (size_t)r * num_nodes + cbase;
                    dst[lane]      = v[r][0];
                    dst[lane + 32] = v[r][1];
                }
                bool m0 = lane < n;
                bool m1 = lane + 32 < n;
#pragma unroll
                for (int r = 0; r < RROWS; r++) {
                    float x0 = m0 ? v[r][0] : NEG_INF;   // __expf(-inf)=0
                    float x1 = m1 ? v[r][1] : NEG_INF;
                    acc[r] = __expf(x0) + __expf(x1);
                }
            } else if (n <= 64) {
                float v[RROWS][2];
#pragma unroll
                for (int r = 0; r < RROWS; r++) {
                    const float* src = srcBase + (size_t)r * num_nodes;
                    v[r][0] = (lane < n)      ? src[cbase + lane]      : NEG_INF;
                    v[r][1] = (lane + 32 < n) ? src[cbase + lane + 32] : NEG_INF;
                }
#pragma unroll
                for (int r = 0; r < RROWS; r++) {
                    float* dst = dstBase + (size_t)r * num_nodes;
                    if (lane < n)      dst[cbase + lane]      = v[r][0];
                    if (lane + 32 < n) dst[cbase + lane + 32] = v[r][1];
                }
#pragma unroll
                for (int r = 0; r < RROWS; r++)
                    acc[r] = __expf(v[r][0]) + __expf(v[r][1]);
            } else {
#pragma unroll
                for (int r = 0; r < RROWS; r++) acc[r] = 0.0f;
                for (int k = lane; k < n; k += 32) {
#pragma unroll
                    for (int r = 0; r < RROWS; r++) {
                        float x = srcBase[(size_t)r * num_nodes + cbase + k];
                        dstBase[(size_t)r * num_nodes + cbase + k] = x;
                        acc[r] += __expf(x);
                    }
                }
            }
            reduce_and_update(acc, lane, pnode, srcBase, dstBase, num_nodes);
        }
    }
    grid_barrier();

    // ---- Phase 1: level-1 parents (children = level-2 nodes, L2-hot) ----
    {
        int total = P1 << 6;
        for (int item = gw; item < total; item += nw)
            upper_seg<2>(in, out, 1, item >> 6, item & 63, lane, num_nodes);
    }
    grid_barrier();

    // ---- Phase 0: root ----
    {
        int total = P0 << 6;
        for (int item = gw; item < total; item += nw)
            upper_seg<4>(in, out, 0, item >> 6, item & 63, lane, num_nodes);
    }
}

extern "C" void kernel_launch(void* const* d_in, const int* in_sizes, int n_in,
                              void* d_out, int out_size) {
    // metadata order: scores, p0,f0,c0,P0,M0, p1,f1,c1,P1,M1, p2,f2,c2,P2,M2
    const float* scores = (const float*)d_in[0];
    const int* p0 = (const int*)d_in[1];
    const int* f0 = (const int*)d_in[2];
    const int* c0 = (const int*)d_in[3];
    const int* M0 = (const int*)d_in[5];
    const int* p1 = (const int*)d_in[6];
    const int* f1 = (const int*)d_in[7];
    const int* c1 = (const int*)d_in[8];
    const int* M1 = (const int*)d_in[10];
    const int* p2 = (const int*)d_in[11];
    const int* f2 = (const int*)d_in[12];
    const int* c2 = (const int*)d_in[13];
    const int* M2 = (const int*)d_in[15];

    int P0 = in_sizes[1],  N0 = in_sizes[2];
    int P1 = in_sizes[6],  N1 = in_sizes[7];
    int P2 = in_sizes[11], N2 = in_sizes[12];
    int num_nodes = in_sizes[0] / BATCH;
    float* out = (float*)d_out;

    // Size the persistent grid to guaranteed-co-resident blocks.
    int sms = 148, occ = 1;
    cudaDeviceGetAttribute(&sms, cudaDevAttrMultiProcessorCount, 0);
    cudaOccupancyMaxActiveBlocksPerMultiprocessor(&occ, fused_kernel, TPB, 0);
    if (occ < 1) occ = 1;
    if (occ > 8) occ = 8;
    int grid = sms * occ;

    fused_kernel<<<grid, TPB>>>(scores, out,
                                f0, M0, c0, p0, N0, P0,
                                f1, M1, c1, p1, N1, P1,
                                f2, M2, c2, p2, N2, P2,
                                num_nodes);
}

// round 11
// speedup vs baseline: 1.4262x; 1.0794x over previous
#include <cuda_runtime.h>
#include <math_constants.h>

#define BATCH 256
#define SEGMAX 8200
#define RROWS 4
#define TPB 256
#define WPB (TPB / 32)

__device__ int g_seg[3][SEGMAX];
__device__ int g_pbase[3];
__device__ int g_cend[3];
__device__ int g_cstart[3];
__device__ unsigned g_barcnt = 0;
__device__ unsigned g_bargen = 0;

// Sense-reversing grid barrier. ALL threads of ALL (co-resident) blocks must call.
__device__ __forceinline__ void grid_barrier() {
    __threadfence();
    __syncthreads();
    if (threadIdx.x == 0) {
        unsigned gen = atomicAdd(&g_bargen, 0u);
        if (atomicAdd(&g_barcnt, 1u) == (unsigned)gridDim.x - 1u) {
            atomicExch(&g_barcnt, 0u);
            __threadfence();
            atomicAdd(&g_bargen, 1u);   // release
        } else {
            while (atomicAdd(&g_bargen, 0u) == gen) { }   // acquire spin
        }
    }
    __syncthreads();
}

// Grouped reduction over 4 row-accumulators + 4 parallel parent updates
// (used by the scalar fallback paths).
__device__ __forceinline__ void reduce_and_update(
    float acc[RROWS], int lane, int pnode,
    const float* srcBase, float* dstBase, int num_nodes) {
#pragma unroll
    for (int r = 0; r < RROWS; r++) {
        acc[r] += __shfl_xor_sync(0xffffffffu, acc[r], 16);
        acc[r] += __shfl_xor_sync(0xffffffffu, acc[r], 8);
    }
    int g = lane >> 3;
    float w = acc[0];
    w = (g == 1) ? acc[1] : w;
    w = (g == 2) ? acc[2] : w;
    w = (g == 3) ? acc[3] : w;
    w += __shfl_xor_sync(0xffffffffu, w, 4);
    w += __shfl_xor_sync(0xffffffffu, w, 2);
    w += __shfl_xor_sync(0xffffffffu, w, 1);
    if ((lane & 7) == 0) {
        float lse = __logf(w);
        const float* rowIn  = srcBase + (size_t)g * num_nodes;
        float*       rowOut = dstBase + (size_t)g * num_nodes;
        rowOut[pnode] = fmaxf(rowIn[pnode], lse);
    }
}

// Upper-level segment LSE (children read from out via __ldcg, cross-SM safe).
template <int SLOTS>
__device__ __forceinline__ void upper_seg(
    const float* __restrict__ in, float* __restrict__ out,
    int lvl, int i, int rg, int lane, int num_nodes) {
    const int* seg = g_seg[lvl];
    int cbase = seg[i];
    int n = seg[i + 1] - cbase;
    int pnode = g_pbase[lvl] + i;
    int cend = g_cend[lvl];

    size_t rowoff = (size_t)(rg * RROWS) * num_nodes;
    const float* srcBase = in + rowoff;
    float*       dstBase = out + rowoff;
    const float NEG_INF = -CUDART_INF_F;
    float acc[RROWS];

    if (n <= SLOTS * 32 && cbase + SLOTS * 32 <= cend) {
        float v[RROWS][SLOTS];
#pragma unroll
        for (int r = 0; r < RROWS; r++) {
            const float* src = dstBase + (size_t)r * num_nodes + cbase;
#pragma unroll
            for (int t = 0; t < SLOTS; t++) v[r][t] = __ldcg(src + lane + t * 32);
        }
#pragma unroll
        for (int r = 0; r < RROWS; r++) {
            acc[r] = 0.0f;
#pragma unroll
            for (int t = 0; t < SLOTS; t++) {
                float x = (lane + t * 32 < n) ? v[r][t] : NEG_INF;
                acc[r] += __expf(x);
            }
        }
    } else {
#pragma unroll
        for (int r = 0; r < RROWS; r++) acc[r] = 0.0f;
        for (int k = lane; k < n; k += 32)
#pragma unroll
            for (int r = 0; r < RROWS; r++)
                acc[r] += __expf(__ldcg(dstBase + (size_t)r * num_nodes + cbase + k));
    }
    reduce_and_update(acc, lane, pnode, srcBase, dstBase, num_nodes);
}

__global__ void __launch_bounds__(TPB)
fused_kernel(const float* __restrict__ in, float* __restrict__ out,
             const int* __restrict__ f0, const int* __restrict__ M0,
             const int* __restrict__ c0, const int* __restrict__ p0, int N0, int P0,
             const int* __restrict__ f1, const int* __restrict__ M1,
             const int* __restrict__ c1, const int* __restrict__ p1, int N1, int P1,
             const int* __restrict__ f2, const int* __restrict__ M2,
             const int* __restrict__ c2, const int* __restrict__ p2, int N2, int P2,
             int num_nodes) {
    int lane = threadIdx.x & 31;
    int gw = blockIdx.x * WPB + (threadIdx.x >> 5);
    int nw = gridDim.x * WPB;
    int tid = blockIdx.x * TPB + threadIdx.x;
    int nthreads = gridDim.x * TPB;

    // ---- Phase P: segment decode for all three levels ----
    {
        int Mv = M2[0];
        for (int k = tid; k < N2; k += nthreads) {
            int i = f2[k] / Mv;
            if (k == 0 || (f2[k - 1] / Mv) != i) g_seg[2][i] = c2[0] + k;
        }
        Mv = M1[0];
        for (int k = tid; k < N1; k += nthreads) {
            int i = f1[k] / Mv;
            if (k == 0 || (f1[k - 1] / Mv) != i) g_seg[1][i] = c1[0] + k;
        }
        Mv = M0[0];
        for (int k = tid; k < N0; k += nthreads) {
            int i = f0[k] / Mv;
            if (k == 0 || (f0[k - 1] / Mv) != i) g_seg[0][i] = c0[0] + k;
        }
        if (tid == 0) {
            g_seg[2][P2] = c2[0] + N2; g_pbase[2] = p2[0]; g_cend[2] = c2[0] + N2; g_cstart[2] = c2[0];
            g_seg[1][P1] = c1[0] + N1; g_pbase[1] = p1[0]; g_cend[1] = c1[0] + N1; g_cstart[1] = c1[0];
            g_seg[0][P0] = c0[0] + N0; g_pbase[0] = p0[0]; g_cend[0] = c0[0] + N0; g_cstart[0] = c0[0];
        }
    }
    grid_barrier();

    // ---- Phase 2 (leaves): fused copy in->out + LSE into level-2 parents ----
    {
        const int* seg = g_seg[2];
        int pbase = g_pbase[2];
        int leafStart = g_cstart[2];
        int leafEnd = g_cend[2];
        const float NEG_INF = -CUDART_INF_F;
        int total = P2 << 6;   // P2 segments x 64 rowgroups
        for (int item = gw; item < total; item += nw) {
            int i = item >> 6;
            int rg = item & 63;
            int cbase = seg[i];
            int n = seg[i + 1] - cbase;
            int pnode = pbase + i;

            if (n <= 61 && cbase >= leafStart + 4 && cbase + 64 <= leafEnd) {
                // === Vectorized fast path ===
                // Half-warp h = lane>>4 owns rows rowA = rg*4+h and rowB = rowA+2.
                // Each row's 64-slot window is aligned DOWN to 16B in flat space;
                // shift in [0,3]. Window stays inside the leaf region (guarded),
                // over-stores write duplicate copied values (benign).
                int half = lane >> 4;
                int q = (lane & 15) << 2;            // element base within window
                size_t rowA = (size_t)(rg * RROWS + half) * num_nodes;
                size_t rowB = rowA + 2u * (unsigned)num_nodes;
                size_t fA = rowA + (unsigned)cbase;
                size_t fB = rowB + (unsigned)cbase;
                int shA = (int)(fA & 3);
                int shB = (int)(fB & 3);
                size_t aA = fA - shA;
                size_t aB = fB - shB;

                float4 vA = *(const float4*)(in + aA + q);
                float4 vB = *(const float4*)(in + aB + q);
                *(float4*)(out + aA + q) = vA;
                *(float4*)(out + aB + q) = vB;

                float accA = 0.0f, accB = 0.0f;
                {
                    float xs[4] = {vA.x, vA.y, vA.z, vA.w};
#pragma unroll
                    for (int c = 0; c < 4; c++) {
                        bool ok = (unsigned)(q + c - shA) < (unsigned)n;
                        accA += __expf(ok ? xs[c] : NEG_INF);
                    }
                }
                {
                    float xs[4] = {vB.x, vB.y, vB.z, vB.w};
#pragma unroll
                    for (int c = 0; c < 4; c++) {
                        bool ok = (unsigned)(q + c - shB) < (unsigned)n;
                        accB += __expf(ok ? xs[c] : NEG_INF);
                    }
                }
                // Butterfly within each 16-lane half.
#pragma unroll
                for (int o = 1; o <= 8; o <<= 1) {
                    accA += __shfl_xor_sync(0xffffffffu, accA, o);
                    accB += __shfl_xor_sync(0xffffffffu, accB, o);
                }
                if ((lane & 15) == 0) {
                    size_t pA = rowA + (unsigned)pnode;
                    size_t pB = rowB + (unsigned)pnode;
                    out[pA] = fmaxf(in[pA], __logf(accA));
                    out[pB] = fmaxf(in[pB], __logf(accB));
                }
            } else {
                // === Scalar predicated path (edge segments / n>61) ===
                size_t rowoff = (size_t)(rg * RROWS) * num_nodes;
                const float* srcBase = in + rowoff;
                float*       dstBase = out + rowoff;
                float acc[RROWS];
                if (n <= 64) {
                    float v[RROWS][2];
#pragma unroll
                    for (int r = 0; r < RROWS; r++) {
                        const float* src = srcBase + (size_t)r * num_nodes;
                        v[r][0] = (lane < n)      ? src[cbase + lane]      : NEG_INF;
                        v[r][1] = (lane + 32 < n) ? src[cbase + lane + 32] : NEG_INF;
                    }
#pragma unroll
                    for (int r = 0; r < RROWS; r++) {
                        float* dst = dstBase + (size_t)r * num_nodes;
                        if (lane < n)      dst[cbase + lane]      = v[r][0];
                        if (lane + 32 < n) dst[cbase + lane + 32] = v[r][1];
                    }
#pragma unroll
                    for (int r = 0; r < RROWS; r++)
                        acc[r] = __expf(v[r][0]) + __expf(v[r][1]);
                } else {
#pragma unroll
                    for (int r = 0; r < RROWS; r++) acc[r] = 0.0f;
                    for (int k = lane; k < n; k += 32) {
#pragma unroll
                        for (int r = 0; r < RROWS; r++) {
                            float x = srcBase[(size_t)r * num_nodes + cbase + k];
                            dstBase[(size_t)r * num_nodes + cbase + k] = x;
                            acc[r] += __expf(x);
                        }
                    }
                }
                reduce_and_update(acc, lane, pnode, srcBase, dstBase, num_nodes);
            }
        }
    }
    grid_barrier();

    // ---- Phase 1: level-1 parents (children = level-2 nodes, L2-hot) ----
    {
        int total = P1 << 6;
        for (int item = gw; item < total; item += nw)
            upper_seg<2>(in, out, 1, item >> 6, item & 63, lane, num_nodes);
    }
    grid_barrier();

    // ---- Phase 0: root ----
    {
        int total = P0 << 6;
        for (int item = gw; item < total; item += nw)
            upper_seg<4>(in, out, 0, item >> 6, item & 63, lane, num_nodes);
    }
}

extern "C" void kernel_launch(void* const* d_in, const int* in_sizes, int n_in,
                              void* d_out, int out_size) {
    // metadata order: scores, p0,f0,c0,P0,M0, p1,f1,c1,P1,M1, p2,f2,c2,P2,M2
    const float* scores = (const float*)d_in[0];
    const int* p0 = (const int*)d_in[1];
    const int* f0 = (const int*)d_in[2];
    const int* c0 = (const int*)d_in[3];
    const int* M0 = (const int*)d_in[5];
    const int* p1 = (const int*)d_in[6];
    const int* f1 = (const int*)d_in[7];
    const int* c1 = (const int*)d_in[8];
    const int* M1 = (const int*)d_in[10];
    const int* p2 = (const int*)d_in[11];
    const int* f2 = (const int*)d_in[12];
    const int* c2 = (const int*)d_in[13];
    const int* M2 = (const int*)d_in[15];

    int P0 = in_sizes[1],  N0 = in_sizes[2];
    int P1 = in_sizes[6],  N1 = in_sizes[7];
    int P2 = in_sizes[11], N2 = in_sizes[12];
    int num_nodes = in_sizes[0] / BATCH;
    float* out = (float*)d_out;

    // Size the persistent grid to guaranteed-co-resident blocks.
    int sms = 148, occ = 1;
    cudaDeviceGetAttribute(&sms, cudaDevAttrMultiProcessorCount, 0);
    cudaOccupancyMaxActiveBlocksPerMultiprocessor(&occ, fused_kernel, TPB, 0);
    if (occ < 1) occ = 1;
    if (occ > 8) occ = 8;
    int grid = sms * occ;

    fused_kernel<<<grid, TPB>>>(scores, out,
                                f0, M0, c0, p0, N0, P0,
                                f1, M1, c1, p1, N1, P1,
                                f2, M2, c2, p2, N2, P2,
                                num_nodes);
}